// round 13
// baseline (speedup 1.0000x reference)
#include <cuda_runtime.h>
#include <cuda_bf16.h>

// Bilateral filter 5x5, sigma_xy = sigma_z = 1, zero padding.
// X: [NC, 512, 512] fp32 (NC = 12), out same shape.
//
// R11 -> R12: SEPARABLE SHIFTABLE BILATERAL (algorithm change).
//   e^{-(p-c)^2/2} = e^{-p^2/2} e^{-c^2/2} e^{pc};  e^{-c^2/2} cancels in num/den.
//   e^{x} on [0,1] ~ deg-4 Chebyshev (err ~5e-5):  e^{pc} ~ sum A_m (pc)^m.
//   => den = sum A_m c^m V_m,  num = sum A_m c^m V_{m+1},
//      V_m = conv2D(w_spatial, e^{-p^2/2} p^m)  -- 6 fields, separable conv.
//   Zero padding is exact: pad pixel -> fields (1,0,0,0,0,0).
// Stages per block (64x16 outputs, 256 threads):
//   A: p tile (68x20) to smem.  B: fused q + horizontal 5-tap conv of the
//   6 fields at pixel-pair positions -> Hs smem.  C: vertical 5-tap conv
//   (symmetric) + packed Horner in c + divide.
// EX2/px: 25 -> ~6.3; MACs/px ~75 vs ~160; slots/SM ~79k vs R4's 107k.

#define IW 512
#define IH 512
#define BW 64
#define BH 16
#define PW (BW + 4)   // 68
#define PH (BH + 4)   // 20

typedef unsigned long long ull;

__device__ __forceinline__ ull pack2(float a, float b) {
    ull r; asm("mov.b64 %0, {%1, %2};" : "=l"(r) : "f"(a), "f"(b)); return r;
}
__device__ __forceinline__ void unpack2(ull v, float& a, float& b) {
    asm("mov.b64 {%0, %1}, %2;" : "=f"(a), "=f"(b) : "l"(v));
}
__device__ __forceinline__ ull fma2(ull a, ull b, ull c) {
    ull d; asm("fma.rn.f32x2 %0, %1, %2, %3;" : "=l"(d) : "l"(a), "l"(b), "l"(c)); return d;
}
__device__ __forceinline__ ull add2(ull a, ull b) {
    ull d; asm("add.rn.f32x2 %0, %1, %2;" : "=l"(d) : "l"(a), "l"(b)); return d;
}
__device__ __forceinline__ ull mul2(ull a, ull b) {
    ull d; asm("mul.rn.f32x2 %0, %1, %2;" : "=l"(d) : "l"(a), "l"(b)); return d;
}
__device__ __forceinline__ float ex2f(float a) {
    float s; asm("ex2.approx.ftz.f32 %0, %1;" : "=f"(s) : "f"(a)); return s;
}
// (hi of a, lo of b)
__device__ __forceinline__ ull mixhl(ull a, ull b) {
    float a0, a1, b0, b1;
    unpack2(a, a0, a1); unpack2(b, b0, b1);
    return pack2(a1, b0);
}

// L = -0.5*log2(e):  e^{-p^2/2} = exp2(L*p^2)
#define LCONST (-0.72134752044448170f)
// 1D spatial weights e^{-k^2/2}, k = -2..2 (symmetric)
#define WAC (0.13533528324f)   // |k|=2
#define WBC (0.60653065971f)   // |k|=1
// deg-4 Chebyshev of e^x on [0,1] (max err ~5e-5)
#define A0C (1.00004084f)
#define A1C (0.99859760f)
#define A2C (0.51009870f)
#define A3C (0.13997540f)
#define A4C (0.06955520f)

__global__ __launch_bounds__(256)
void bilateral_kernel(const float* __restrict__ X, float* __restrict__ out)
{
    __shared__ __align__(8) float pt[PH][PW];
    __shared__ ull Hs[PH][6][BW / 2];   // horizontal-conv fields, pixel-pairs

    const int z = blockIdx.z;
    const float* __restrict__ img = X + (size_t)z * IH * IW;
    const int gx0 = blockIdx.x * BW - 2;
    const int gy0 = blockIdx.y * BH - 2;
    const int tid = threadIdx.x;

    // ---- Stage A: p tile with zero pad ----
    #pragma unroll
    for (int i = tid; i < PH * PW; i += 256) {
        const int sy = i / PW;
        const int sx = i - sy * PW;
        const int gx = gx0 + sx;
        const int gy = gy0 + sy;
        float v = 0.0f;
        if ((unsigned)gx < IW && (unsigned)gy < IH) v = img[gy * IW + gx];
        pt[sy][sx] = v;
    }
    __syncthreads();

    const ull L2  = pack2(LCONST, LCONST);
    const ull WA2 = pack2(WAC, WAC);
    const ull WB2 = pack2(WBC, WBC);

    // ---- Stage B: q + horizontal conv, pixel-pair positions (32 x PH) ----
    #pragma unroll
    for (int i = tid; i < 32 * PH; i += 256) {
        const int row  = i >> 5;
        const int cpiB = i & 31;
        const int cp   = cpiB * 2;

        // window p cols for outputs (cp, cp+1): cp .. cp+5
        const ull P0 = *(const ull*)&pt[row][cp];
        const ull P1 = *(const ull*)&pt[row][cp + 2];
        const ull P2 = *(const ull*)&pt[row][cp + 4];
        const ull T1 = mixhl(P0, P1);
        const ull T3 = mixhl(P1, P2);

        const ull z2 = pack2(0.0f, 0.0f);
        ull h0 = z2, h1 = z2, h2 = z2, h3 = z2, h4 = z2, h5 = z2;

        // one horizontal tap: q = wx * e^{-f^2/2}; fields h_m += q * f^m
        #define BTAP(T, WM) {                                   \
            const ull u2 = mul2(T, T);                          \
            const ull a2 = mul2(u2, L2);                        \
            float aa, ab; unpack2(a2, aa, ab);                  \
            ull t2 = pack2(ex2f(aa), ex2f(ab));                 \
            WM                                                  \
            h0 = add2(h0, t2); t2 = mul2(t2, T);                \
            h1 = add2(h1, t2); t2 = mul2(t2, T);                \
            h2 = add2(h2, t2); t2 = mul2(t2, T);                \
            h3 = add2(h3, t2); t2 = mul2(t2, T);                \
            h4 = add2(h4, t2); t2 = mul2(t2, T);                \
            h5 = add2(h5, t2); }
        BTAP(P0, t2 = mul2(t2, WA2);)
        BTAP(T1, t2 = mul2(t2, WB2);)
        BTAP(P1, )
        BTAP(T3, t2 = mul2(t2, WB2);)
        BTAP(P2, t2 = mul2(t2, WA2);)
        #undef BTAP

        Hs[row][0][cpiB] = h0;
        Hs[row][1][cpiB] = h1;
        Hs[row][2][cpiB] = h2;
        Hs[row][3][cpiB] = h3;
        Hs[row][4][cpiB] = h4;
        Hs[row][5][cpiB] = h5;
    }
    __syncthreads();

    // ---- Stage C: vertical conv (2 output rows) + Horner + divide ----
    const int cpi = tid & 31;
    const int cp  = cpi * 2;
    const int ry  = (tid >> 5) * 2;     // output rows ry, ry+1

    ull V0m[6], V1m[6];
    #pragma unroll
    for (int m = 0; m < 6; m++) {
        const ull g0 = Hs[ry + 0][m][cpi];
        const ull g1 = Hs[ry + 1][m][cpi];
        const ull g2 = Hs[ry + 2][m][cpi];
        const ull g3 = Hs[ry + 3][m][cpi];
        const ull g4 = Hs[ry + 4][m][cpi];
        const ull g5 = Hs[ry + 5][m][cpi];
        V0m[m] = fma2(WA2, add2(g0, g4), fma2(WB2, add2(g1, g3), g2));
        V1m[m] = fma2(WA2, add2(g1, g5), fma2(WB2, add2(g2, g4), g3));
    }

    const ull A0_2 = pack2(A0C, A0C);
    const ull A1_2 = pack2(A1C, A1C);
    const ull A2_2 = pack2(A2C, A2C);
    const ull A3_2 = pack2(A3C, A3C);
    const ull A4_2 = pack2(A4C, A4C);

    #define OUTPAIR(Vm, K) {                                            \
        const ull c2 = *(const ull*)&pt[ry + (K) + 2][cp + 2];          \
        ull td = mul2(A4_2, Vm[4]);                                     \
        td = fma2(c2, td, mul2(A3_2, Vm[3]));                           \
        td = fma2(c2, td, mul2(A2_2, Vm[2]));                           \
        td = fma2(c2, td, mul2(A1_2, Vm[1]));                           \
        const ull den2 = fma2(c2, td, mul2(A0_2, Vm[0]));               \
        ull tn = mul2(A4_2, Vm[5]);                                     \
        tn = fma2(c2, tn, mul2(A3_2, Vm[4]));                           \
        tn = fma2(c2, tn, mul2(A2_2, Vm[3]));                           \
        tn = fma2(c2, tn, mul2(A1_2, Vm[2]));                           \
        const ull num2 = fma2(c2, tn, mul2(A0_2, Vm[1]));               \
        float n0, n1, d0, d1;                                           \
        unpack2(num2, n0, n1); unpack2(den2, d0, d1);                   \
        float2 r;                                                       \
        r.x = __fdividef(n0, d0);                                       \
        r.y = __fdividef(n1, d1);                                       \
        const int gx = blockIdx.x * BW + cp;                            \
        const int gy = blockIdx.y * BH + ry + (K);                      \
        *(float2*)&out[(size_t)z * IH * IW + gy * IW + gx] = r; }

    OUTPAIR(V0m, 0)
    OUTPAIR(V1m, 1)
    #undef OUTPAIR
}

extern "C" void kernel_launch(void* const* d_in, const int* in_sizes, int n_in,
                              void* d_out, int out_size)
{
    const float* X = (const float*)d_in[0];
    float* out = (float*)d_out;

    const int NC = in_sizes[0] / (IH * IW);   // 12 for (4,3,512,512)

    dim3 block(256);
    dim3 grid(IW / BW, IH / BH, NC);
    bilateral_kernel<<<grid, block>>>(X, out);
}

// round 15
// speedup vs baseline: 1.0367x; 1.0367x over previous
#include <cuda_runtime.h>
#include <cuda_bf16.h>

// Bilateral filter 5x5, sigma_xy = sigma_z = 1, zero padding.
// X: [NC, 512, 512] fp32 (NC = 12), out same shape.
//
// Separable shiftable bilateral:
//   e^{-(p-c)^2/2} = e^{-p^2/2} e^{-c^2/2} e^{pc};  e^{-c^2/2} cancels.
//   e^{x} on [0,1] ~ deg-4 Chebyshev:  den = sum_k A_k c^k V_k,
//   num = sum_{k=1..5} A_{k-1} c^{k-1} V_k,  V_k = conv2D(w_xy, e^{-p^2/2} p^k).
//
// R14 fix: stored fields are H_k = A_k*V_k (H5 = A4*V5). That makes the
// den Horner coefficient-free; the NUM Horner must use the shifted
// coefficients A_{k-1} = R_k * A_k, i.e. each num term needs R_k = A_{k-1}/A_k:
//   num = H5 c^4 + R4 H4 c^3 + R3 H3 c^2 + R2 H2 c + R1 H1.
// (R13 wrongly fed H_k straight into num -> rel_err 0.18.)
// Keeps R13's wins: fused vertical-conv Horner (no V[6] arrays), ILP BTAP
// (powers independent of EX2, 6-way fma fan-out).

#define IW 512
#define IH 512
#define BW 64
#define BH 16
#define PW (BW + 4)   // 68
#define PH (BH + 4)   // 20

typedef unsigned long long ull;

__device__ __forceinline__ ull pack2(float a, float b) {
    ull r; asm("mov.b64 %0, {%1, %2};" : "=l"(r) : "f"(a), "f"(b)); return r;
}
__device__ __forceinline__ void unpack2(ull v, float& a, float& b) {
    asm("mov.b64 {%0, %1}, %2;" : "=f"(a), "=f"(b) : "l"(v));
}
__device__ __forceinline__ ull fma2(ull a, ull b, ull c) {
    ull d; asm("fma.rn.f32x2 %0, %1, %2, %3;" : "=l"(d) : "l"(a), "l"(b), "l"(c)); return d;
}
__device__ __forceinline__ ull add2(ull a, ull b) {
    ull d; asm("add.rn.f32x2 %0, %1, %2;" : "=l"(d) : "l"(a), "l"(b)); return d;
}
__device__ __forceinline__ ull mul2(ull a, ull b) {
    ull d; asm("mul.rn.f32x2 %0, %1, %2;" : "=l"(d) : "l"(a), "l"(b)); return d;
}
__device__ __forceinline__ float ex2f(float a) {
    float s; asm("ex2.approx.ftz.f32 %0, %1;" : "=f"(s) : "f"(a)); return s;
}
// (hi of a, lo of b)
__device__ __forceinline__ ull mixhl(ull a, ull b) {
    float a0, a1, b0, b1;
    unpack2(a, a0, a1); unpack2(b, b0, b1);
    return pack2(a1, b0);
}

// L = -0.5*log2(e):  e^{-p^2/2} = exp2(L*p^2)
#define LCONST (-0.72134752044448170f)
// 1D spatial weights e^{-k^2/2}
#define WAC (0.13533528324f)   // |k|=2
#define WBC (0.60653065971f)   // |k|=1
// deg-4 Chebyshev of e^x on [0,1] (max err ~5e-5)
#define A0C (1.00004084f)
#define A1C (0.99859760f)
#define A2C (0.51009870f)
#define A3C (0.13997540f)
#define A4C (0.06955520f)
// num-Horner ratio constants R_k = A_{k-1}/A_k
#define R1C (1.0014453f)
#define R2C (1.9576563f)
#define R3C (3.6442024f)
#define R4C (2.0124362f)

__global__ __launch_bounds__(256)
void bilateral_kernel(const float* __restrict__ X, float* __restrict__ out)
{
    __shared__ __align__(8) float pt[PH][PW];
    __shared__ ull Hs[PH][6][BW / 2];   // H_k = A_k * (horizontal field k)

    const int z = blockIdx.z;
    const float* __restrict__ img = X + (size_t)z * IH * IW;
    const int gx0 = blockIdx.x * BW - 2;
    const int gy0 = blockIdx.y * BH - 2;
    const int tid = threadIdx.x;

    // ---- Stage A: p tile with zero pad ----
    #pragma unroll
    for (int i = tid; i < PH * PW; i += 256) {
        const int sy = i / PW;
        const int sx = i - sy * PW;
        const int gx = gx0 + sx;
        const int gy = gy0 + sy;
        float v = 0.0f;
        if ((unsigned)gx < IW && (unsigned)gy < IH) v = img[gy * IW + gx];
        pt[sy][sx] = v;
    }
    __syncthreads();

    const ull L2  = pack2(LCONST, LCONST);
    const ull WA2 = pack2(WAC, WAC);
    const ull WB2 = pack2(WBC, WBC);

    // ---- Stage B: q + horizontal conv at pixel-pair positions ----
    #pragma unroll
    for (int i = tid; i < 32 * PH; i += 256) {
        const int row  = i >> 5;
        const int cpiB = i & 31;
        const int cp   = cpiB * 2;

        const ull P0 = *(const ull*)&pt[row][cp];
        const ull P1 = *(const ull*)&pt[row][cp + 2];
        const ull P2 = *(const ull*)&pt[row][cp + 4];
        const ull T1 = mixhl(P0, P1);
        const ull T3 = mixhl(P1, P2);

        const ull z2 = pack2(0.0f, 0.0f);
        ull h0 = z2, h1 = z2, h2 = z2, h3 = z2, h4 = z2, h5 = z2;

        // tap: q = wx * e^{-p^2/2}; powers independent of EX2; 6-way fan-out
        #define BTAP(T, WM) {                                   \
            const ull u2 = mul2(T, T);                          \
            const ull a2 = mul2(u2, L2);                        \
            const ull p3 = mul2(u2, T);                         \
            const ull p4 = mul2(u2, u2);                        \
            const ull p5 = mul2(p3, u2);                        \
            float aa, ab; unpack2(a2, aa, ab);                  \
            ull q = pack2(ex2f(aa), ex2f(ab));                  \
            WM                                                  \
            h0 = add2(h0, q);                                   \
            h1 = fma2(q, T,  h1);                               \
            h2 = fma2(q, u2, h2);                               \
            h3 = fma2(q, p3, h3);                               \
            h4 = fma2(q, p4, h4);                               \
            h5 = fma2(q, p5, h5); }
        BTAP(P0, q = mul2(q, WA2);)
        BTAP(T1, q = mul2(q, WB2);)
        BTAP(P1, )
        BTAP(T3, q = mul2(q, WB2);)
        BTAP(P2, q = mul2(q, WA2);)
        #undef BTAP

        // prescale by Chebyshev coefficients (den-exact form)
        Hs[row][0][cpiB] = mul2(h0, pack2(A0C, A0C));
        Hs[row][1][cpiB] = mul2(h1, pack2(A1C, A1C));
        Hs[row][2][cpiB] = mul2(h2, pack2(A2C, A2C));
        Hs[row][3][cpiB] = mul2(h3, pack2(A3C, A3C));
        Hs[row][4][cpiB] = mul2(h4, pack2(A4C, A4C));
        Hs[row][5][cpiB] = mul2(h5, pack2(A4C, A4C));  // num leading term
    }
    __syncthreads();

    // ---- Stage C: fused vertical conv + Horner (fields k = 5 .. 0) ----
    // den = H0 + c H1 + c^2 H2 + c^3 H3 + c^4 H4            (coefficient-free)
    // num = H5 c^4 + R4 H4 c^3 + R3 H3 c^2 + R2 H2 c + R1 H1 (ratio-corrected)
    const int cpi = tid & 31;
    const int cp  = cpi * 2;
    const int ry  = (tid >> 5) * 2;     // output rows ry, ry+1

    const ull c20 = *(const ull*)&pt[ry + 2][cp + 2];
    const ull c21 = *(const ull*)&pt[ry + 3][cp + 2];

    const ull R1_2 = pack2(R1C, R1C);
    const ull R2_2 = pack2(R2C, R2C);
    const ull R3_2 = pack2(R3C, R3C);
    const ull R4_2 = pack2(R4C, R4C);

    // vertical 5-tap conv of field k for the two rows
    #define FIELD(k, V0, V1)                                            \
        ull V0, V1;                                                     \
        {                                                               \
            const ull g0 = Hs[ry + 0][k][cpi];                          \
            const ull g1 = Hs[ry + 1][k][cpi];                          \
            const ull g2 = Hs[ry + 2][k][cpi];                          \
            const ull g3 = Hs[ry + 3][k][cpi];                          \
            const ull g4 = Hs[ry + 4][k][cpi];                          \
            const ull g5 = Hs[ry + 5][k][cpi];                          \
            V0 = fma2(WA2, add2(g0, g4), fma2(WB2, add2(g1, g3), g2));  \
            V1 = fma2(WA2, add2(g1, g5), fma2(WB2, add2(g2, g4), g3));  \
        }

    ull tn0, tn1, td0, td1;
    { FIELD(5, V0, V1)
      tn0 = V0;                                   tn1 = V1; }
    { FIELD(4, V0, V1)
      tn0 = fma2(c20, tn0, mul2(R4_2, V0));       tn1 = fma2(c21, tn1, mul2(R4_2, V1));
      td0 = V0;                                   td1 = V1; }
    { FIELD(3, V0, V1)
      tn0 = fma2(c20, tn0, mul2(R3_2, V0));       tn1 = fma2(c21, tn1, mul2(R3_2, V1));
      td0 = fma2(c20, td0, V0);                   td1 = fma2(c21, td1, V1); }
    { FIELD(2, V0, V1)
      tn0 = fma2(c20, tn0, mul2(R2_2, V0));       tn1 = fma2(c21, tn1, mul2(R2_2, V1));
      td0 = fma2(c20, td0, V0);                   td1 = fma2(c21, td1, V1); }
    { FIELD(1, V0, V1)
      tn0 = fma2(c20, tn0, mul2(R1_2, V0));       tn1 = fma2(c21, tn1, mul2(R1_2, V1));
      td0 = fma2(c20, td0, V0);                   td1 = fma2(c21, td1, V1); }
    { FIELD(0, V0, V1)
      td0 = fma2(c20, td0, V0);                   td1 = fma2(c21, td1, V1); }
    #undef FIELD

    float n0, n1, d0, d1;
    float2 r;
    const int gx = blockIdx.x * BW + cp;
    const size_t obase = (size_t)z * IH * IW + gx;

    unpack2(tn0, n0, n1); unpack2(td0, d0, d1);
    r.x = __fdividef(n0, d0);
    r.y = __fdividef(n1, d1);
    *(float2*)&out[obase + (size_t)(blockIdx.y * BH + ry) * IW] = r;

    unpack2(tn1, n0, n1); unpack2(td1, d0, d1);
    r.x = __fdividef(n0, d0);
    r.y = __fdividef(n1, d1);
    *(float2*)&out[obase + (size_t)(blockIdx.y * BH + ry + 1) * IW] = r;
}

extern "C" void kernel_launch(void* const* d_in, const int* in_sizes, int n_in,
                              void* d_out, int out_size)
{
    const float* X = (const float*)d_in[0];
    float* out = (float*)d_out;

    const int NC = in_sizes[0] / (IH * IW);   // 12 for (4,3,512,512)

    dim3 block(256);
    dim3 grid(IW / BW, IH / BH, NC);
    bilateral_kernel<<<grid, block>>>(X, out);
}

// round 17
// speedup vs baseline: 1.1222x; 1.0824x over previous
#include <cuda_runtime.h>
#include <cuda_bf16.h>

// Bilateral filter 5x5, sigma_xy = sigma_z = 1, zero padding.
// X: [NC, 512, 512] fp32 (NC = 12), out same shape.
//
// Separable shiftable bilateral:
//   e^{-(p-c)^2/2} = e^{-p^2/2} e^{-c^2/2} e^{pc};  e^{-c^2/2} cancels.
//   R15 -> R16: deg-4 -> DEG-3 Chebyshev of e^x on [0,1] (max err 5.5e-4;
//   measured 11x attenuation through num/den -> ~5e-5 output rel err).
//   FIELDS: 6 -> 5.  den = sum_{k=0..3} A_k c^k V_k,
//   num = sum_{k=0..3} A_k c^k V_{k+1},  V_k = conv2D(w_xy, e^{-p^2/2} p^k).
//   Stored prescaled: H_k = A_k V_k (H4 = A3 V4) -> den Horner coefficient-
//   free; num Horner uses ratios R_k = A_{k-1}/A_k.
// Cuts stage-B fma and field stores by 17%, stage-C crossbar reads by 17%
// (L1 was the top pipe at 52%), smem 36->31KB, and register pressure
// (one fewer packed accumulator + power + 1 fewer R const).

#define IW 512
#define IH 512
#define BW 64
#define BH 16
#define PW (BW + 4)   // 68
#define PH (BH + 4)   // 20

typedef unsigned long long ull;

__device__ __forceinline__ ull pack2(float a, float b) {
    ull r; asm("mov.b64 %0, {%1, %2};" : "=l"(r) : "f"(a), "f"(b)); return r;
}
__device__ __forceinline__ void unpack2(ull v, float& a, float& b) {
    asm("mov.b64 {%0, %1}, %2;" : "=f"(a), "=f"(b) : "l"(v));
}
__device__ __forceinline__ ull fma2(ull a, ull b, ull c) {
    ull d; asm("fma.rn.f32x2 %0, %1, %2, %3;" : "=l"(d) : "l"(a), "l"(b), "l"(c)); return d;
}
__device__ __forceinline__ ull add2(ull a, ull b) {
    ull d; asm("add.rn.f32x2 %0, %1, %2;" : "=l"(d) : "l"(a), "l"(b)); return d;
}
__device__ __forceinline__ ull mul2(ull a, ull b) {
    ull d; asm("mul.rn.f32x2 %0, %1, %2;" : "=l"(d) : "l"(a), "l"(b)); return d;
}
__device__ __forceinline__ float ex2f(float a) {
    float s; asm("ex2.approx.ftz.f32 %0, %1;" : "=f"(s) : "f"(a)); return s;
}
// (hi of a, lo of b)
__device__ __forceinline__ ull mixhl(ull a, ull b) {
    float a0, a1, b0, b1;
    unpack2(a, a0, a1); unpack2(b, b0, b1);
    return pack2(a1, b0);
}

// L = -0.5*log2(e):  e^{-p^2/2} = exp2(L*p^2)
#define LCONST (-0.72134752044448170f)
// 1D spatial weights e^{-k^2/2}
#define WAC (0.13533528324f)   // |k|=2
#define WBC (0.60653065971f)   // |k|=1
// deg-3 Chebyshev-derived minimax of e^x on [0,1] (max err ~5.5e-4)
#define A0C (0.999508f)
#define A1C (1.015947f)
#define A2C (0.423156f)
#define A3C (0.279106f)
// num-Horner ratio constants R_k = A_{k-1}/A_k
#define R1C (0.983817f)
#define R2C (2.400875f)
#define R3C (1.516113f)

__global__ __launch_bounds__(256)
void bilateral_kernel(const float* __restrict__ X, float* __restrict__ out)
{
    __shared__ __align__(8) float pt[PH][PW];
    __shared__ ull Hs[PH][5][BW / 2];   // H_k = A_k * (horizontal field k)

    const int z = blockIdx.z;
    const float* __restrict__ img = X + (size_t)z * IH * IW;
    const int gx0 = blockIdx.x * BW - 2;
    const int gy0 = blockIdx.y * BH - 2;
    const int tid = threadIdx.x;

    // ---- Stage A: p tile with zero pad ----
    #pragma unroll
    for (int i = tid; i < PH * PW; i += 256) {
        const int sy = i / PW;
        const int sx = i - sy * PW;
        const int gx = gx0 + sx;
        const int gy = gy0 + sy;
        float v = 0.0f;
        if ((unsigned)gx < IW && (unsigned)gy < IH) v = img[gy * IW + gx];
        pt[sy][sx] = v;
    }
    __syncthreads();

    const ull L2  = pack2(LCONST, LCONST);
    const ull WA2 = pack2(WAC, WAC);
    const ull WB2 = pack2(WBC, WBC);

    // ---- Stage B: q + horizontal conv at pixel-pair positions ----
    #pragma unroll
    for (int i = tid; i < 32 * PH; i += 256) {
        const int row  = i >> 5;
        const int cpiB = i & 31;
        const int cp   = cpiB * 2;

        const ull P0 = *(const ull*)&pt[row][cp];
        const ull P1 = *(const ull*)&pt[row][cp + 2];
        const ull P2 = *(const ull*)&pt[row][cp + 4];
        const ull T1 = mixhl(P0, P1);
        const ull T3 = mixhl(P1, P2);

        const ull z2 = pack2(0.0f, 0.0f);
        ull h0 = z2, h1 = z2, h2 = z2, h3 = z2, h4 = z2;

        // tap: q = wx * e^{-p^2/2}; powers independent of EX2; 5-way fan-out
        #define BTAP(T, WM) {                                   \
            const ull u2 = mul2(T, T);                          \
            const ull a2 = mul2(u2, L2);                        \
            const ull p3 = mul2(u2, T);                         \
            const ull p4 = mul2(u2, u2);                        \
            float aa, ab; unpack2(a2, aa, ab);                  \
            ull q = pack2(ex2f(aa), ex2f(ab));                  \
            WM                                                  \
            h0 = add2(h0, q);                                   \
            h1 = fma2(q, T,  h1);                               \
            h2 = fma2(q, u2, h2);                               \
            h3 = fma2(q, p3, h3);                               \
            h4 = fma2(q, p4, h4); }
        BTAP(P0, q = mul2(q, WA2);)
        BTAP(T1, q = mul2(q, WB2);)
        BTAP(P1, )
        BTAP(T3, q = mul2(q, WB2);)
        BTAP(P2, q = mul2(q, WA2);)
        #undef BTAP

        // prescale by Chebyshev coefficients (den-exact form)
        Hs[row][0][cpiB] = mul2(h0, pack2(A0C, A0C));
        Hs[row][1][cpiB] = mul2(h1, pack2(A1C, A1C));
        Hs[row][2][cpiB] = mul2(h2, pack2(A2C, A2C));
        Hs[row][3][cpiB] = mul2(h3, pack2(A3C, A3C));
        Hs[row][4][cpiB] = mul2(h4, pack2(A3C, A3C));  // num leading term
    }
    __syncthreads();

    // ---- Stage C: fused vertical conv + Horner (fields k = 4 .. 0) ----
    // den = H0 + c H1 + c^2 H2 + c^3 H3                     (coefficient-free)
    // num = H4 c^3 + R3 H3 c^2 + R2 H2 c + R1 H1            (ratio-corrected)
    const int cpi = tid & 31;
    const int cp  = cpi * 2;
    const int ry  = (tid >> 5) * 2;     // output rows ry, ry+1

    const ull c20 = *(const ull*)&pt[ry + 2][cp + 2];
    const ull c21 = *(const ull*)&pt[ry + 3][cp + 2];

    const ull R1_2 = pack2(R1C, R1C);
    const ull R2_2 = pack2(R2C, R2C);
    const ull R3_2 = pack2(R3C, R3C);

    // vertical 5-tap conv of field k for the two rows
    #define FIELD(k, V0, V1)                                            \
        ull V0, V1;                                                     \
        {                                                               \
            const ull g0 = Hs[ry + 0][k][cpi];                          \
            const ull g1 = Hs[ry + 1][k][cpi];                          \
            const ull g2 = Hs[ry + 2][k][cpi];                          \
            const ull g3 = Hs[ry + 3][k][cpi];                          \
            const ull g4 = Hs[ry + 4][k][cpi];                          \
            const ull g5 = Hs[ry + 5][k][cpi];                          \
            V0 = fma2(WA2, add2(g0, g4), fma2(WB2, add2(g1, g3), g2));  \
            V1 = fma2(WA2, add2(g1, g5), fma2(WB2, add2(g2, g4), g3));  \
        }

    ull tn0, tn1, td0, td1;
    { FIELD(4, V0, V1)
      tn0 = V0;                                   tn1 = V1; }
    { FIELD(3, V0, V1)
      tn0 = fma2(c20, tn0, mul2(R3_2, V0));       tn1 = fma2(c21, tn1, mul2(R3_2, V1));
      td0 = V0;                                   td1 = V1; }
    { FIELD(2, V0, V1)
      tn0 = fma2(c20, tn0, mul2(R2_2, V0));       tn1 = fma2(c21, tn1, mul2(R2_2, V1));
      td0 = fma2(c20, td0, V0);                   td1 = fma2(c21, td1, V1); }
    { FIELD(1, V0, V1)
      tn0 = fma2(c20, tn0, mul2(R1_2, V0));       tn1 = fma2(c21, tn1, mul2(R1_2, V1));
      td0 = fma2(c20, td0, V0);                   td1 = fma2(c21, td1, V1); }
    { FIELD(0, V0, V1)
      td0 = fma2(c20, td0, V0);                   td1 = fma2(c21, td1, V1); }
    #undef FIELD

    float n0, n1, d0, d1;
    float2 r;
    const int gx = blockIdx.x * BW + cp;
    const size_t obase = (size_t)z * IH * IW + gx;

    unpack2(tn0, n0, n1); unpack2(td0, d0, d1);
    r.x = __fdividef(n0, d0);
    r.y = __fdividef(n1, d1);
    *(float2*)&out[obase + (size_t)(blockIdx.y * BH + ry) * IW] = r;

    unpack2(tn1, n0, n1); unpack2(td1, d0, d1);
    r.x = __fdividef(n0, d0);
    r.y = __fdividef(n1, d1);
    *(float2*)&out[obase + (size_t)(blockIdx.y * BH + ry + 1) * IW] = r;
}

extern "C" void kernel_launch(void* const* d_in, const int* in_sizes, int n_in,
                              void* d_out, int out_size)
{
    const float* X = (const float*)d_in[0];
    float* out = (float*)d_out;

    const int NC = in_sizes[0] / (IH * IW);   // 12 for (4,3,512,512)

    dim3 block(256);
    dim3 grid(IW / BW, IH / BH, NC);
    bilateral_kernel<<<grid, block>>>(X, out);
}